// round 7
// baseline (speedup 1.0000x reference)
#include <cuda_runtime.h>

// LineGraphic2d: distance-field line segment on 8192x8192 fp32 canvas.
// Mask must be BIT-EXACT vs XLA ref (one flipped pixel = 5e-3 rel_err):
//   exact chain = unfused fp32 + div.full.f32, mask via e2 < 9.0f
//   (sqrt.rn is monotone & correctly rounded, 9=3^2 exact => dist<3 <=> e2<9).
// Fast path (all pixels): FMA + rcp math; re-decide with the exact chain only
// when |e2_fast - 9| < 0.5 (fast-path error near contour ~6e-3 << 0.5).
// Value side needs only ~1e-4 accuracy: dist via MUFU.RSQ, 1/maxd multiply.

#define H 8192
#define W 8192
#define EPSILON_F 0.001f

__device__ __forceinline__ float div_full(float a, float b) {
    float r;
    asm("div.full.f32 %0, %1, %2;" : "=f"(r) : "f"(a), "f"(b));
    return r;
}

__global__ void __launch_bounds__(256) line2d_kernel(
    const float* __restrict__ kp, float4* __restrict__ out)
{
    const int idx = blockIdx.x * blockDim.x + threadIdx.x;  // one float4 = 4 pixels
    const int pix = idx << 2;
    const int y = pix >> 13;          // / 8192
    const int x = pix & (W - 1);      // % 8192

    // key_points [2,2]: rows=(p0,p1), cols=(y,x). x8192 = power-of-two: exact,
    // so p0, d match the reference's fp32 scalars bit-for-bit.
    const float4 k = *reinterpret_cast<const float4*>(kp);
    const float p0y = __fmul_rn(k.x, (float)H);
    const float p0x = __fmul_rn(k.y, (float)W);
    const float dy  = __fsub_rn(__fmul_rn(k.z, (float)H), p0y);
    const float dx  = __fsub_rn(__fmul_rn(k.w, (float)W), p0x);
    // Ref rounding: len2 = d0*d0 + d1*d1 unfused
    const float len2 = __fadd_rn(__fmul_rn(dy, dy), __fmul_rn(dx, dx));
    const float inv_len2 = __frcp_rn(len2);
    const float inv_maxd = __frcp_rn(__fsqrt_rn(134217728.0f));   // 1/norm([8192,8192])

    const float ry = __fsub_rn((float)y, p0y);
    const float ry_dy = __fmul_rn(ry, dy);    // ref's per-row product (exact-path reuse)

    float4 o;
    float* op = &o.x;
    #pragma unroll
    for (int j = 0; j < 4; ++j) {
        const float rx = __fsub_rn((float)(x + j), p0x);

        // ---- fast path (FMA + rcp) ----
        float t = __fmaf_rn(rx, dx, ry_dy) * inv_len2;
        t = fminf(fmaxf(t, 0.0f), 1.0f);
        float ey = __fmaf_rn(-t, dy, ry);
        float ex = __fmaf_rn(-t, dx, rx);
        float e2 = fmaxf(__fmaf_rn(ey, ey, ex * ex), 1e-12f);

        bool inside = e2 < 9.0f;

        // ---- exact re-decide near the contour (ref's bit-exact chain) ----
        if (fabsf(e2 - 9.0f) < 0.5f) {
            float te = div_full(__fadd_rn(ry_dy, __fmul_rn(rx, dx)), len2);
            te = fminf(fmaxf(te, 0.0f), 1.0f);
            const float eye = __fsub_rn(ry, __fmul_rn(te, dy));
            const float exe = __fsub_rn(rx, __fmul_rn(te, dx));
            const float e2e = fmaxf(__fadd_rn(__fmul_rn(eye, eye), __fmul_rn(exe, exe)), 1e-12f);
            inside = e2e < 9.0f;
        }

        // ---- value (approx ok: needs only ~1e-4 abs accuracy) ----
        const float dist = e2 * __frsqrt_rn(e2);          // ~1e-6 rel, no sqrt.rn
        const float v = __fmaf_rn(-dist, inv_maxd, 1.0f - EPSILON_F);
        op[j] = inside ? v : 0.0f;
    }
    out[idx] = o;
}

extern "C" void kernel_launch(void* const* d_in, const int* in_sizes, int n_in,
                              void* d_out, int out_size)
{
    const float* kp = (const float*)d_in[0];
    float4* out = (float4*)d_out;
    const int n_vec4 = (H * W) / 4;          // 16,777,216 float4 stores
    const int threads = 256;
    const int blocks = n_vec4 / threads;     // 65,536 blocks
    line2d_kernel<<<blocks, threads>>>(kp, out);
}

// round 8
// speedup vs baseline: 2.7914x; 2.7914x over previous
#include <cuda_runtime.h>

// LineGraphic2d: 8192x8192 fp32 canvas, 6px-wide capsule is nonzero (0.06%).
// Strategy: zero-fill at store bandwidth; per 4-pixel cluster do ONE fast
// midpoint point-to-segment test; only band clusters (~0.25%) run the
// bit-exact XLA-matching chain (unfused fp32 + div.full.f32, mask e2 < 9).
// Mask bit-exactness requirement: one flipped pixel = 5e-3 rel_err (>1e-3).

#define H 8192
#define W 8192
#define EPSILON_F 0.001f

__device__ __forceinline__ float div_full(float a, float b) {
    float r;
    asm("div.full.f32 %0, %1, %2;" : "=f"(r) : "f"(a), "f"(b));
    return r;
}

__global__ void __launch_bounds__(256) line2d_kernel(
    const float* __restrict__ kp, float4* __restrict__ out)
{
    // Block covers 1024 consecutive float4 = 4096 px = half a row (uniform y).
    const int block_base = blockIdx.x << 10;            // float4 index
    const int y = (block_base << 2) >> 13;              // row (same for whole block)
    const int tid = threadIdx.x;

    // key_points [2,2]: rows=(p0,p1), cols=(y,x). x8192 = power-of-two: exact,
    // so p0, d match the reference's fp32 scalars bit-for-bit.
    const float4 k = *reinterpret_cast<const float4*>(kp);
    const float p0y = __fmul_rn(k.x, (float)H);
    const float p0x = __fmul_rn(k.y, (float)W);
    const float dy  = __fsub_rn(__fmul_rn(k.z, (float)H), p0y);
    const float dx  = __fsub_rn(__fmul_rn(k.w, (float)W), p0x);
    const float len2 = __fadd_rn(__fmul_rn(dy, dy), __fmul_rn(dx, dx));   // ref rounding
    const float inv_len2 = __frcp_rn(len2);
    const float inv_maxd = __frcp_rn(__fsqrt_rn(134217728.0f));           // 1/norm([8192,8192])

    const float ry = __fsub_rn((float)y, p0y);
    const float ry_dy = __fmul_rn(ry, dy);              // ref's per-row product

    #pragma unroll
    for (int q = 0; q < 4; ++q) {
        const int v4 = block_base + (q << 8) + tid;     // coalesced: lane-stride 16B
        const int x = (v4 << 2) & (W - 1);

        // ---- one fast midpoint test per 4-px cluster ----
        const float rxm = ((float)x + 1.5f) - p0x;
        float tm = __fmaf_rn(rxm, dx, ry_dy) * inv_len2;
        tm = fminf(fmaxf(tm, 0.0f), 1.0f);
        const float eym = __fmaf_rn(-tm, dy, ry);
        const float exm = __fmaf_rn(-tm, dx, rxm);
        const float e2m = __fmaf_rn(eym, eym, exm * exm);

        float4 o = make_float4(0.0f, 0.0f, 0.0f, 0.0f);
        if (e2m < 30.25f) {   // dist_mid < 5.5 = 3 + 1.5 (cluster) + 1.0 (margin)
            float* op = &o.x;
            #pragma unroll
            for (int j = 0; j < 4; ++j) {
                // bit-exact ref chain: unfused fp32 + div.full.f32
                const float rx = __fsub_rn((float)(x + j), p0x);
                float t = div_full(__fadd_rn(ry_dy, __fmul_rn(rx, dx)), len2);
                t = fminf(fmaxf(t, 0.0f), 1.0f);
                const float ey = __fsub_rn(ry, __fmul_rn(t, dy));
                const float ex = __fsub_rn(rx, __fmul_rn(t, dx));
                const float e2 = fmaxf(__fadd_rn(__fmul_rn(ey, ey), __fmul_rn(ex, ex)), 1e-12f);
                // mask: dist<3 <=> e2<9 (sqrt.rn monotone, 9 exact)
                const float dist = __fsqrt_rn(e2);
                const float v = 1.0f - __fmaf_rn(dist, inv_maxd, EPSILON_F);
                op[j] = (e2 < 9.0f) ? v : 0.0f;
            }
        }
        out[v4] = o;
    }
}

extern "C" void kernel_launch(void* const* d_in, const int* in_sizes, int n_in,
                              void* d_out, int out_size)
{
    const float* kp = (const float*)d_in[0];
    float4* out = (float4*)d_out;
    const int n_vec4 = (H * W) / 4;          // 16,777,216 float4
    const int blocks = n_vec4 / 1024;        // 16,384 blocks, 256 threads, 4 f4/thread
    line2d_kernel<<<blocks, 256>>>(kp, out);
}

// round 9
// speedup vs baseline: 2.8002x; 1.0031x over previous
#include <cuda_runtime.h>

// LineGraphic2d: 8192x8192 fp32 canvas, 6px-wide capsule nonzero (0.06%).
// R8 structure (cluster midpoint test -> zero-fill or bit-exact band chain)
// + R9: one row per CTA (8 float4/thread), st.global.cs streaming stores to
// keep the 256MB write stream from thrashing L2.
// Mask bit-exactness: unfused fp32 + div.full.f32, e2 < 9 (== dist < 3).

#define H 8192
#define W 8192
#define EPSILON_F 0.001f

__device__ __forceinline__ float div_full(float a, float b) {
    float r;
    asm("div.full.f32 %0, %1, %2;" : "=f"(r) : "f"(a), "f"(b));
    return r;
}

__device__ __forceinline__ void stg_cs_128(float4* p, float4 v) {
    asm volatile("st.global.cs.v4.f32 [%0], {%1, %2, %3, %4};"
                 :: "l"(p), "f"(v.x), "f"(v.y), "f"(v.z), "f"(v.w) : "memory");
}

__global__ void __launch_bounds__(256) line2d_kernel(
    const float* __restrict__ kp, float4* __restrict__ out)
{
    // One full row per block: 8192 px = 2048 float4 = 256 threads x 8.
    const int y = blockIdx.x;
    const int row_base = y << 11;                       // float4 index of row start
    const int tid = threadIdx.x;

    // key_points [2,2]: rows=(p0,p1), cols=(y,x). x8192 = power-of-two: exact,
    // so p0, d match the reference's fp32 scalars bit-for-bit.
    const float4 k = *reinterpret_cast<const float4*>(kp);
    const float p0y = __fmul_rn(k.x, (float)H);
    const float p0x = __fmul_rn(k.y, (float)W);
    const float dy  = __fsub_rn(__fmul_rn(k.z, (float)H), p0y);
    const float dx  = __fsub_rn(__fmul_rn(k.w, (float)W), p0x);
    const float len2 = __fadd_rn(__fmul_rn(dy, dy), __fmul_rn(dx, dx));   // ref rounding
    const float inv_len2 = __frcp_rn(len2);
    const float inv_maxd = __frcp_rn(__fsqrt_rn(134217728.0f));           // 1/norm([8192,8192])

    const float ry = __fsub_rn((float)y, p0y);
    const float ry_dy = __fmul_rn(ry, dy);              // ref's per-row product

    #pragma unroll
    for (int q = 0; q < 8; ++q) {
        const int v4 = row_base + (q << 8) + tid;       // coalesced: lane-stride 16B
        const int x = (v4 << 2) & (W - 1);

        // ---- one fast midpoint test per 4-px cluster ----
        const float rxm = ((float)x + 1.5f) - p0x;
        float tm = __fmaf_rn(rxm, dx, ry_dy) * inv_len2;
        tm = fminf(fmaxf(tm, 0.0f), 1.0f);
        const float eym = __fmaf_rn(-tm, dy, ry);
        const float exm = __fmaf_rn(-tm, dx, rxm);
        const float e2m = __fmaf_rn(eym, eym, exm * exm);

        float4 o = make_float4(0.0f, 0.0f, 0.0f, 0.0f);
        if (e2m < 30.25f) {   // dist_mid < 5.5 = 3 + 1.5 (cluster) + 1.0 (margin)
            float* op = &o.x;
            #pragma unroll
            for (int j = 0; j < 4; ++j) {
                // bit-exact ref chain: unfused fp32 + div.full.f32
                const float rx = __fsub_rn((float)(x + j), p0x);
                float t = div_full(__fadd_rn(ry_dy, __fmul_rn(rx, dx)), len2);
                t = fminf(fmaxf(t, 0.0f), 1.0f);
                const float ey = __fsub_rn(ry, __fmul_rn(t, dy));
                const float ex = __fsub_rn(rx, __fmul_rn(t, dx));
                const float e2 = fmaxf(__fadd_rn(__fmul_rn(ey, ey), __fmul_rn(ex, ex)), 1e-12f);
                // mask: dist<3 <=> e2<9 (sqrt.rn monotone, 9 exact)
                const float dist = __fsqrt_rn(e2);
                const float v = 1.0f - __fmaf_rn(dist, inv_maxd, EPSILON_F);
                op[j] = (e2 < 9.0f) ? v : 0.0f;
            }
        }
        stg_cs_128(&out[v4], o);    // streaming: don't pollute L2 with write stream
    }
}

extern "C" void kernel_launch(void* const* d_in, const int* in_sizes, int n_in,
                              void* d_out, int out_size)
{
    const float* kp = (const float*)d_in[0];
    float4* out = (float4*)d_out;
    line2d_kernel<<<H, 256>>>(kp, out);     // one block per row
}

// round 10
// speedup vs baseline: 2.8023x; 1.0008x over previous
#include <cuda_runtime.h>

// LineGraphic2d: 8192x8192 fp32 canvas, 6px-wide capsule nonzero (0.06%).
// R10: 8-pixel clusters with 256-bit streaming stores (st.global.cs.v8.f32,
// Blackwell STG.256) to halve L1 store wavefronts (L1 was the binding pipe at
// 74.6%). One midpoint point-to-segment test per cluster; band clusters run
// the bit-exact XLA chain (unfused fp32 + div.full.f32, mask e2 < 9).

#define H 8192
#define W 8192
#define EPSILON_F 0.001f

__device__ __forceinline__ float div_full(float a, float b) {
    float r;
    asm("div.full.f32 %0, %1, %2;" : "=f"(r) : "f"(a), "f"(b));
    return r;
}

__device__ __forceinline__ void stg_cs_256(float* p, const float* v) {
    asm volatile("st.global.cs.v8.f32 [%0], {%1, %2, %3, %4, %5, %6, %7, %8};"
                 :: "l"(p), "f"(v[0]), "f"(v[1]), "f"(v[2]), "f"(v[3]),
                            "f"(v[4]), "f"(v[5]), "f"(v[6]), "f"(v[7])
                 : "memory");
}

__global__ void __launch_bounds__(256) line2d_kernel(
    const float* __restrict__ kp, float* __restrict__ out)
{
    // One full row per block: 8192 px = 1024 float8 = 256 threads x 4.
    const int y = blockIdx.x;
    const int tid = threadIdx.x;

    // key_points [2,2]: rows=(p0,p1), cols=(y,x). x8192 = power-of-two: exact,
    // so p0, d match the reference's fp32 scalars bit-for-bit.
    const float4 k = *reinterpret_cast<const float4*>(kp);
    const float p0y = __fmul_rn(k.x, (float)H);
    const float p0x = __fmul_rn(k.y, (float)W);
    const float dy  = __fsub_rn(__fmul_rn(k.z, (float)H), p0y);
    const float dx  = __fsub_rn(__fmul_rn(k.w, (float)W), p0x);
    const float len2 = __fadd_rn(__fmul_rn(dy, dy), __fmul_rn(dx, dx));   // ref rounding
    const float inv_len2 = __frcp_rn(len2);
    const float inv_maxd = __frcp_rn(__fsqrt_rn(134217728.0f));           // 1/norm([8192,8192])

    const float ry = __fsub_rn((float)y, p0y);
    const float ry_dy = __fmul_rn(ry, dy);              // ref's per-row product

    #pragma unroll
    for (int q = 0; q < 4; ++q) {
        const int v8 = (y << 10) + (q << 8) + tid;      // float8 index; warp: 1KB contig
        const int x = (v8 << 3) & (W - 1);              // cluster start pixel

        // ---- one fast midpoint test per 8-px cluster ----
        const float rxm = ((float)x + 3.5f) - p0x;
        float tm = __fmaf_rn(rxm, dx, ry_dy) * inv_len2;
        tm = fminf(fmaxf(tm, 0.0f), 1.0f);
        const float eym = __fmaf_rn(-tm, dy, ry);
        const float exm = __fmaf_rn(-tm, dx, rxm);
        const float e2m = __fmaf_rn(eym, eym, exm * exm);

        float o[8] = {0.f, 0.f, 0.f, 0.f, 0.f, 0.f, 0.f, 0.f};
        if (e2m < 56.25f) {   // dist_mid < 7.5 = 3 + 3.5 (cluster radius) + 1 (margin)
            #pragma unroll
            for (int j = 0; j < 8; ++j) {
                // bit-exact ref chain: unfused fp32 + div.full.f32
                const float rx = __fsub_rn((float)(x + j), p0x);
                float t = div_full(__fadd_rn(ry_dy, __fmul_rn(rx, dx)), len2);
                t = fminf(fmaxf(t, 0.0f), 1.0f);
                const float ey = __fsub_rn(ry, __fmul_rn(t, dy));
                const float ex = __fsub_rn(rx, __fmul_rn(t, dx));
                const float e2 = fmaxf(__fadd_rn(__fmul_rn(ey, ey), __fmul_rn(ex, ex)), 1e-12f);
                // mask: dist<3 <=> e2<9 (sqrt.rn monotone, 9 exact)
                const float dist = __fsqrt_rn(e2);
                const float v = 1.0f - __fmaf_rn(dist, inv_maxd, EPSILON_F);
                o[j] = (e2 < 9.0f) ? v : 0.0f;
            }
        }
        stg_cs_256(out + ((size_t)v8 << 3), o);   // STG.256, 32B-aligned
    }
}

extern "C" void kernel_launch(void* const* d_in, const int* in_sizes, int n_in,
                              void* d_out, int out_size)
{
    const float* kp = (const float*)d_in[0];
    float* out = (float*)d_out;
    line2d_kernel<<<H, 256>>>(kp, out);     // one block per row
}